// round 1
// baseline (speedup 1.0000x reference)
#include <cuda_runtime.h>
#include <math.h>

#define B_      4096
#define SEQ_    59
#define FEAT_   64
#define U_      1024
#define VOCAB_  578
#define NPAD    640
#define KTOT    1088            // U_ + FEAT_
#define N4U     4096            // 4*U_
#define XROW    (SEQ_*FEAT_)    // per-batch row stride of x

// ---------------- device scratch (no allocations allowed) ----------------
__device__ float g_Wp[KTOT * N4U];       // permuted [rec; kernel], cols n=4u+g
__device__ float g_biasp[N4U];           // permuted bias
__device__ float g_h[2][B_ * U_];        // double-buffered hidden state
__device__ float g_c[B_ * U_];           // cell state (in-place)
__device__ float g_w2p[U_ * NPAD];       // w2 padded to 640 cols
__device__ float g_b2p[NPAD];
__device__ float g_logits[B_ * NPAD];

// ---------------- weight permutation (runs every launch; ~trivial) -------
__global__ void permute_weights(const float* __restrict__ kernel,
                                const float* __restrict__ rec_kernel,
                                const float* __restrict__ bias,
                                const float* __restrict__ w2,
                                const float* __restrict__ b2) {
    int stride = gridDim.x * blockDim.x;
    int idx = blockIdx.x * blockDim.x + threadIdx.x;

    // W' [KTOT][4096]: col n = 4u+g  <-  source col g*U + u
    for (int i = idx; i < KTOT * N4U; i += stride) {
        int k = i >> 12;            // / 4096
        int n = i & 4095;
        int u = n >> 2, g = n & 3;
        int src = g * U_ + u;
        g_Wp[i] = (k < U_) ? rec_kernel[k * N4U + src]
                           : kernel[(k - U_) * N4U + src];
    }
    for (int n = idx; n < N4U; n += stride) {
        int u = n >> 2, g = n & 3;
        g_biasp[n] = bias[g * U_ + u];
    }
    for (int i = idx; i < U_ * NPAD; i += stride) {
        int k = i / NPAD, v = i - k * NPAD;
        g_w2p[i] = (v < VOCAB_) ? w2[k * VOCAB_ + v] : 0.f;
    }
    for (int v = idx; v < NPAD; v += stride)
        g_b2p[v] = (v < VOCAB_) ? b2[v] : 0.f;
}

__global__ void zero_state() {
    int stride = gridDim.x * blockDim.x;
    int idx = blockIdx.x * blockDim.x + threadIdx.x;
    for (int i = idx; i < B_ * U_; i += stride) {
        g_h[0][i] = 0.f;
        g_c[i]    = 0.f;
    }
}

__device__ __forceinline__ float sigmoidf_(float x) {
    return 1.f / (1.f + expf(-x));
}

// ---------------- fused LSTM step: Z = [h|x_t] @ W' ; gates in epilogue ---
// 128x128 tile, K-tile 8, 256 threads, 8x8 per-thread microtile.
__global__ void __launch_bounds__(256, 2)
lstm_step(const float* __restrict__ x, int t, int hin_idx) {
    const float* __restrict__ hin = g_h[hin_idx];
    float* __restrict__ hout = g_h[hin_idx ^ 1];

    __shared__ __align__(16) float As[8][128];   // A tile transposed: As[k][m]
    __shared__ __align__(16) float Bs[8][128];   // B tile: Bs[k][n]

    const int tid = threadIdx.x;
    const int tx = tid & 15;       // 16 threads in N
    const int ty = tid >> 4;       // 16 threads in M
    const int mbase = blockIdx.y * 128;
    const int nbase = blockIdx.x * 128;

    float acc[8][8];
    #pragma unroll
    for (int i = 0; i < 8; i++)
        #pragma unroll
        for (int j = 0; j < 8; j++) acc[i][j] = 0.f;

    const int arow = tid >> 1;            // 0..127
    const int acol = (tid & 1) << 2;      // 0 or 4
    const int brow = tid >> 5;            // 0..7
    const int bcol = (tid & 31) << 2;     // 0..124

    for (int k0 = 0; k0 < KTOT; k0 += 8) {
        // ---- load A tile (128 x 8), transposed into As[k][m]
        int grow = mbase + arow;
        int gk = k0 + acol;
        float4 av;
        if (gk < U_) {
            av = *reinterpret_cast<const float4*>(hin + (size_t)grow * U_ + gk);
        } else {
            av = *reinterpret_cast<const float4*>(
                x + (size_t)grow * XROW + t * FEAT_ + (gk - U_));
        }
        As[acol + 0][arow] = av.x;
        As[acol + 1][arow] = av.y;
        As[acol + 2][arow] = av.z;
        As[acol + 3][arow] = av.w;

        // ---- load B tile (8 x 128)
        float4 bv = *reinterpret_cast<const float4*>(
            g_Wp + (size_t)(k0 + brow) * N4U + nbase + bcol);
        *reinterpret_cast<float4*>(&Bs[brow][bcol]) = bv;

        __syncthreads();

        #pragma unroll
        for (int kk = 0; kk < 8; kk++) {
            float a[8], b[8];
            const float4* Av = reinterpret_cast<const float4*>(&As[kk][ty * 8]);
            const float4* Bv = reinterpret_cast<const float4*>(&Bs[kk][tx * 8]);
            float4 a0 = Av[0], a1 = Av[1];
            float4 b0 = Bv[0], b1 = Bv[1];
            a[0]=a0.x; a[1]=a0.y; a[2]=a0.z; a[3]=a0.w;
            a[4]=a1.x; a[5]=a1.y; a[6]=a1.z; a[7]=a1.w;
            b[0]=b0.x; b[1]=b0.y; b[2]=b0.z; b[3]=b0.w;
            b[4]=b1.x; b[5]=b1.y; b[6]=b1.z; b[7]=b1.w;
            #pragma unroll
            for (int i = 0; i < 8; i++)
                #pragma unroll
                for (int j = 0; j < 8; j++)
                    acc[i][j] = fmaf(a[i], b[j], acc[i][j]);
        }
        __syncthreads();
    }

    // ---- epilogue: per-thread cols are [tx*8, tx*8+8) = 2 u's x 4 gates
    #pragma unroll
    for (int i = 0; i < 8; i++) {
        int b_idx = mbase + ty * 8 + i;
        #pragma unroll
        for (int uu = 0; uu < 2; uu++) {
            int n0 = nbase + tx * 8 + uu * 4;   // gate-0 column; n0 % 4 == 0
            int u = n0 >> 2;
            float zi = acc[i][uu * 4 + 0] + g_biasp[n0 + 0];
            float zf = acc[i][uu * 4 + 1] + g_biasp[n0 + 1];
            float zg = acc[i][uu * 4 + 2] + g_biasp[n0 + 2];
            float zo = acc[i][uu * 4 + 3] + g_biasp[n0 + 3];
            float ig = sigmoidf_(zi);
            float fg = sigmoidf_(zf);
            float gg = tanhf(zg);
            float og = sigmoidf_(zo);
            size_t cidx = (size_t)b_idx * U_ + u;
            float cn = fg * g_c[cidx] + ig * gg;
            g_c[cidx]  = cn;
            hout[cidx] = og * tanhf(cn);
        }
    }
}

// ---------------- final dense: logits = h_last @ w2p + b2p ---------------
__global__ void __launch_bounds__(256, 2)
dense2(int h_idx) {
    const float* __restrict__ A = g_h[h_idx];

    __shared__ __align__(16) float As[8][128];
    __shared__ __align__(16) float Bs[8][128];

    const int tid = threadIdx.x;
    const int tx = tid & 15;
    const int ty = tid >> 4;
    const int mbase = blockIdx.y * 128;
    const int nbase = blockIdx.x * 128;

    float acc[8][8];
    #pragma unroll
    for (int i = 0; i < 8; i++)
        #pragma unroll
        for (int j = 0; j < 8; j++) acc[i][j] = 0.f;

    const int arow = tid >> 1;
    const int acol = (tid & 1) << 2;
    const int brow = tid >> 5;
    const int bcol = (tid & 31) << 2;

    for (int k0 = 0; k0 < U_; k0 += 8) {
        int grow = mbase + arow;
        float4 av = *reinterpret_cast<const float4*>(
            A + (size_t)grow * U_ + k0 + acol);
        As[acol + 0][arow] = av.x;
        As[acol + 1][arow] = av.y;
        As[acol + 2][arow] = av.z;
        As[acol + 3][arow] = av.w;

        float4 bv = *reinterpret_cast<const float4*>(
            g_w2p + (size_t)(k0 + brow) * NPAD + nbase + bcol);
        *reinterpret_cast<float4*>(&Bs[brow][bcol]) = bv;

        __syncthreads();

        #pragma unroll
        for (int kk = 0; kk < 8; kk++) {
            float a[8], b[8];
            const float4* Av = reinterpret_cast<const float4*>(&As[kk][ty * 8]);
            const float4* Bv = reinterpret_cast<const float4*>(&Bs[kk][tx * 8]);
            float4 a0 = Av[0], a1 = Av[1];
            float4 b0 = Bv[0], b1 = Bv[1];
            a[0]=a0.x; a[1]=a0.y; a[2]=a0.z; a[3]=a0.w;
            a[4]=a1.x; a[5]=a1.y; a[6]=a1.z; a[7]=a1.w;
            b[0]=b0.x; b[1]=b0.y; b[2]=b0.z; b[3]=b0.w;
            b[4]=b1.x; b[5]=b1.y; b[6]=b1.z; b[7]=b1.w;
            #pragma unroll
            for (int i = 0; i < 8; i++)
                #pragma unroll
                for (int j = 0; j < 8; j++)
                    acc[i][j] = fmaf(a[i], b[j], acc[i][j]);
        }
        __syncthreads();
    }

    #pragma unroll
    for (int i = 0; i < 8; i++) {
        int b_idx = mbase + ty * 8 + i;
        #pragma unroll
        for (int j = 0; j < 8; j++) {
            int n = nbase + tx * 8 + j;
            g_logits[(size_t)b_idx * NPAD + n] = acc[i][j] + g_b2p[n];
        }
    }
}

// ---------------- softmax over 578 logits per batch row -------------------
__global__ void softmax_kernel(float* __restrict__ out) {
    const int b = blockIdx.x;
    const float* __restrict__ l = g_logits + (size_t)b * NPAD;
    __shared__ float red[256];
    const int tid = threadIdx.x;

    float m = -1e30f;
    for (int v = tid; v < VOCAB_; v += 256) m = fmaxf(m, l[v]);
    red[tid] = m;
    __syncthreads();
    for (int s = 128; s > 0; s >>= 1) {
        if (tid < s) red[tid] = fmaxf(red[tid], red[tid + s]);
        __syncthreads();
    }
    float mx = red[0];
    __syncthreads();

    float sum = 0.f;
    for (int v = tid; v < VOCAB_; v += 256) sum += expf(l[v] - mx);
    red[tid] = sum;
    __syncthreads();
    for (int s = 128; s > 0; s >>= 1) {
        if (tid < s) red[tid] += red[tid + s];
        __syncthreads();
    }
    float inv = 1.f / red[0];

    for (int v = tid; v < VOCAB_; v += 256)
        out[(size_t)b * VOCAB_ + v] = expf(l[v] - mx) * inv;
}

// ---------------- launch --------------------------------------------------
extern "C" void kernel_launch(void* const* d_in, const int* in_sizes, int n_in,
                              void* d_out, int out_size) {
    const float* x      = (const float*)d_in[0];
    const float* kernel = (const float*)d_in[1];
    const float* rec    = (const float*)d_in[2];
    const float* bias   = (const float*)d_in[3];
    const float* w2     = (const float*)d_in[4];
    const float* b2     = (const float*)d_in[5];
    float* out = (float*)d_out;

    permute_weights<<<2048, 256>>>(kernel, rec, bias, w2, b2);
    zero_state<<<2048, 256>>>();

    dim3 grid(N4U / 128, B_ / 128);   // 32 x 32
    for (int s = 0; s < SEQ_; s++)
        lstm_step<<<grid, 256>>>(x, s, s & 1);

    dense2<<<dim3(NPAD / 128, B_ / 128), 256>>>(SEQ_ & 1);
    softmax_kernel<<<B_, 256>>>(out);
}